// round 3
// baseline (speedup 1.0000x reference)
#include <cuda_runtime.h>

// MeanShift: B=2, C=3, N=9216, 5 iterations.
// w_ij = exp2( (2g*y_i).x_j + (-g*||x_j||^2) + (-g*||y_i||^2) ), g = 50/ln2.
// FMA pipe and MUFU are exactly balanced at 4 f32x2 + 1 EX2 per pair
// (73.7K cyc/iter/SM floor). This round: 512 threads, 2 queries per thread
// -> two independent dep chains per loaded j-pair (ILP x2), LDS/loop
// overhead per pair halved, 128-reg ceiling instead of 64.

#define NPTS 9216
#define NB 2
#define GG 72.13475204444817f   // 50 / ln(2)
#define NSPLIT 8
#define CHUNK (NPTS / NSPLIT)   // 1152 points per chunk

typedef unsigned long long u64;

__device__ float4 g_pts[NB * NPTS];      // [2*jp+0]={x0,x1,y0,y1}, [2*jp+1]={z0,z1,b0,b1}
__device__ float4 g_y[2][NB * NPTS];

__device__ __forceinline__ float ex2f(float x) {
    float r; asm("ex2.approx.ftz.f32 %0, %1;" : "=f"(r) : "f"(x)); return r;
}
__device__ __forceinline__ u64 pk2(float a, float b) {
    u64 r; asm("mov.b64 %0, {%1,%2};" : "=l"(r) : "f"(a), "f"(b)); return r;
}
__device__ __forceinline__ void upk2(u64 v, float& a, float& b) {
    asm("mov.b64 {%0,%1}, %2;" : "=f"(a), "=f"(b) : "l"(v));
}
__device__ __forceinline__ u64 fma2(u64 a, u64 b, u64 c) {
    u64 d; asm("fma.rn.f32x2 %0, %1, %2, %3;" : "=l"(d) : "l"(a), "l"(b), "l"(c)); return d;
}
__device__ __forceinline__ u64 add2(u64 a, u64 b) {
    u64 d; asm("add.rn.f32x2 %0, %1, %2;" : "=l"(d) : "l"(a), "l"(b)); return d;
}

__global__ void prep_kernel(const float* __restrict__ x) {
    int idx = blockIdx.x * blockDim.x + threadIdx.x;
    if (idx >= NB * NPTS) return;
    int b = idx / NPTS, n = idx - b * NPTS;
    float px = x[(b * 3 + 0) * NPTS + n];
    float py = x[(b * 3 + 1) * NPTS + n];
    float pz = x[(b * 3 + 2) * NPTS + n];
    float bn = -GG * (px * px + py * py + pz * pz);
    int jp = n >> 1, l = n & 1;
    float* base = (float*)&g_pts[b * NPTS + 2 * jp];
    base[0 + l] = px;   // {x0,x1, y0,y1}
    base[2 + l] = py;
    base[4 + l] = pz;   // {z0,z1, b0,b1}
    base[6 + l] = bn;
    g_y[0][b * NPTS + n] = make_float4(px, py, pz, 0.f);
}

// Grid: (72 query-tiles, 2 batches), 512 threads = 64 q-slots x 8 j-chunks,
// each thread owns 2 queries (q, q+64). Chunk id uniform per warp -> all
// LDS.128 are full-warp broadcasts.
__global__ __launch_bounds__(512, 1) void iter_kernel(int src, int dst, float* __restrict__ out) {
    extern __shared__ float4 sm[];          // [0,NPTS): points, then 8*128 partials
    float4* psum = sm + NPTS;
    const int b = blockIdx.y;

    const float4* gp = g_pts + b * NPTS;
    for (int i = threadIdx.x; i < NPTS; i += 512) sm[i] = gp[i];
    __syncthreads();

    const int ql = threadIdx.x & 63;        // query slot (q0=ql, q1=ql+64)
    const int s = threadIdx.x >> 6;         // j-chunk id (uniform within warp)
    const int qg0 = blockIdx.x * 128 + ql;
    const int qg1 = qg0 + 64;

    const float tg = 2.0f * GG;
    float4 y0 = g_y[src][b * NPTS + qg0];
    float4 y1 = g_y[src][b * NPTS + qg1];
    const u64 ax0 = pk2(tg * y0.x, tg * y0.x);
    const u64 ay0 = pk2(tg * y0.y, tg * y0.y);
    const u64 az0 = pk2(tg * y0.z, tg * y0.z);
    const float p0 = -GG * (y0.x * y0.x + y0.y * y0.y + y0.z * y0.z);
    const u64 pp0 = pk2(p0, p0);
    const u64 ax1 = pk2(tg * y1.x, tg * y1.x);
    const u64 ay1 = pk2(tg * y1.y, tg * y1.y);
    const u64 az1 = pk2(tg * y1.z, tg * y1.z);
    const float p1 = -GG * (y1.x * y1.x + y1.y * y1.y + y1.z * y1.z);
    const u64 pp1 = pk2(p1, p1);

    u64 a0x = 0ull, a0y = 0ull, a0z = 0ull, a0w = 0ull;
    u64 a1x = 0ull, a1y = 0ull, a1z = 0ull, a1w = 0ull;

    const float4* smp = sm + s * CHUNK;     // s * 1152 float4s (2 per point-pair)
    #pragma unroll 2
    for (int i = 0; i < CHUNK / 2; i++) {   // 576 steps, 2 points x 2 queries
        float4 ab0 = smp[2 * i + 0];        // {x0,x1,y0,y1}
        float4 ab1 = smp[2 * i + 1];        // {z0,z1,b0,b1}
        u64 xx = pk2(ab0.x, ab0.y);
        u64 yy = pk2(ab0.z, ab0.w);
        u64 zz = pk2(ab1.x, ab1.y);
        u64 bb = pk2(ab1.z, ab1.w);

        u64 t0 = add2(bb, pp0);
        t0 = fma2(az0, zz, t0);
        t0 = fma2(ay0, yy, t0);
        t0 = fma2(ax0, xx, t0);
        u64 t1 = add2(bb, pp1);
        t1 = fma2(az1, zz, t1);
        t1 = fma2(ay1, yy, t1);
        t1 = fma2(ax1, xx, t1);

        float u0, u1, v0, v1;
        upk2(t0, u0, u1);
        upk2(t1, v0, v1);
        u64 w0 = pk2(ex2f(u0), ex2f(u1));   // 4x MUFU EX2 total
        u64 w1 = pk2(ex2f(v0), ex2f(v1));

        a0x = fma2(w0, xx, a0x);
        a0y = fma2(w0, yy, a0y);
        a0z = fma2(w0, zz, a0z);
        a0w = add2(a0w, w0);
        a1x = fma2(w1, xx, a1x);
        a1y = fma2(w1, yy, a1y);
        a1z = fma2(w1, zz, a1z);
        a1w = add2(a1w, w1);
    }

    float e0, e1;
    upk2(a0x, e0, e1); float s0x = e0 + e1;
    upk2(a0y, e0, e1); float s0y = e0 + e1;
    upk2(a0z, e0, e1); float s0z = e0 + e1;
    upk2(a0w, e0, e1); float s0w = e0 + e1;
    psum[s * 128 + ql] = make_float4(s0x, s0y, s0z, s0w);
    upk2(a1x, e0, e1); float s1x = e0 + e1;
    upk2(a1y, e0, e1); float s1y = e0 + e1;
    upk2(a1z, e0, e1); float s1z = e0 + e1;
    upk2(a1w, e0, e1); float s1w = e0 + e1;
    psum[s * 128 + ql + 64] = make_float4(s1x, s1y, s1z, s1w);
    __syncthreads();

    // Reduce the 8 chunk-partials per query.
    if (threadIdx.x < 128) {
        float4 a = psum[threadIdx.x];
        #pragma unroll
        for (int k = 1; k < NSPLIT; k++) {
            float4 p2 = psum[k * 128 + threadIdx.x];
            a.x += p2.x; a.y += p2.y; a.z += p2.z; a.w += p2.w;
        }
        float inv = __fdividef(1.0f, a.w);
        float nx = a.x * inv, ny = a.y * inv, nz = a.z * inv;
        int qi = blockIdx.x * 128 + threadIdx.x;
        g_y[dst][b * NPTS + qi] = make_float4(nx, ny, nz, 0.f);
        if (out) {
            out[(b * 3 + 0) * NPTS + qi] = nx;
            out[(b * 3 + 1) * NPTS + qi] = ny;
            out[(b * 3 + 2) * NPTS + qi] = nz;
        }
    }
}

extern "C" void kernel_launch(void* const* d_in, const int* in_sizes, int n_in,
                              void* d_out, int out_size) {
    const float* x = (const float*)d_in[0];
    float* out = (float*)d_out;

    const size_t smem = (size_t)(NPTS + 1024) * sizeof(float4);  // 163840 B
    cudaFuncSetAttribute(iter_kernel, cudaFuncAttributeMaxDynamicSharedMemorySize, (int)smem);

    prep_kernel<<<(NB * NPTS + 255) / 256, 256>>>(x);

    dim3 grid(72, NB);
    for (int it = 0; it < 5; it++) {
        iter_kernel<<<grid, 512, smem>>>(it & 1, (it & 1) ^ 1, (it == 4) ? out : nullptr);
    }
}

// round 4
// speedup vs baseline: 1.0139x; 1.0139x over previous
#include <cuda_runtime.h>
#include <cstdint>

// MeanShift: B=2, C=3, N=9216, 5 iterations.
// w_ij = exp2( (2g*y_i).x_j + (-g*||x_j||^2) + (-g*||y_i||^2) ), g = 50/ln2.
// Per-iter per-SM floors: FMA-pipe ~71.8K cyc == MUFU ~71.8K cyc (balanced).
// R4: kill the pack/unpack MOV tax (alu was 21%) -- load point pairs natively
// as u64 via ld.shared.v2.u64, run ex2 in place on the f32x2 register pair.
// 768 threads = 64 q-slots x 12 j-chunks, 2 queries/thread, grid 144.

#define NPTS 9216
#define NB 2
#define GG 72.13475204444817f   // 50 / ln(2)
#define NSPLIT 12
#define CHUNK (NPTS / NSPLIT)   // 768 points per chunk

typedef unsigned long long u64;

__device__ float4 g_pts[NB * NPTS];      // [2*jp+0]={x0,x1,y0,y1}, [2*jp+1]={z0,z1,b0,b1}
__device__ float4 g_y[2][NB * NPTS];

__device__ __forceinline__ u64 pk2(float a, float b) {
    u64 r; asm("mov.b64 %0, {%1,%2};" : "=l"(r) : "f"(a), "f"(b)); return r;
}
__device__ __forceinline__ void upk2(u64 v, float& a, float& b) {
    asm("mov.b64 {%0,%1}, %2;" : "=f"(a), "=f"(b) : "l"(v));
}
__device__ __forceinline__ u64 fma2(u64 a, u64 b, u64 c) {
    u64 d; asm("fma.rn.f32x2 %0, %1, %2, %3;" : "=l"(d) : "l"(a), "l"(b), "l"(c)); return d;
}
__device__ __forceinline__ u64 add2(u64 a, u64 b) {
    u64 d; asm("add.rn.f32x2 %0, %1, %2;" : "=l"(d) : "l"(a), "l"(b)); return d;
}
// exp2 on both halves of an f32x2 pair, in place (self-moves fold away).
__device__ __forceinline__ void ex2_pair(u64& t) {
    asm("{\n\t"
        ".reg .f32 lo, hi;\n\t"
        "mov.b64 {lo, hi}, %0;\n\t"
        "ex2.approx.ftz.f32 lo, lo;\n\t"
        "ex2.approx.ftz.f32 hi, hi;\n\t"
        "mov.b64 %0, {lo, hi};\n\t"
        "}" : "+l"(t));
}
__device__ __forceinline__ void lds_2u64(unsigned addr, u64& a, u64& b) {
    asm("ld.shared.v2.u64 {%0, %1}, [%2];" : "=l"(a), "=l"(b) : "r"(addr));
}

__global__ void prep_kernel(const float* __restrict__ x) {
    int idx = blockIdx.x * blockDim.x + threadIdx.x;
    if (idx >= NB * NPTS) return;
    int b = idx / NPTS, n = idx - b * NPTS;
    float px = x[(b * 3 + 0) * NPTS + n];
    float py = x[(b * 3 + 1) * NPTS + n];
    float pz = x[(b * 3 + 2) * NPTS + n];
    float bn = -GG * (px * px + py * py + pz * pz);
    int jp = n >> 1, l = n & 1;
    float* base = (float*)&g_pts[b * NPTS + 2 * jp];
    base[0 + l] = px;   // {x0,x1, y0,y1}
    base[2 + l] = py;
    base[4 + l] = pz;   // {z0,z1, b0,b1}
    base[6 + l] = bn;
    g_y[0][b * NPTS + n] = make_float4(px, py, pz, 0.f);
}

// Grid: (72 query-tiles, 2 batches), 768 threads = 64 q-slots x 12 j-chunks,
// each thread owns 2 queries (ql, ql+64). Chunk id uniform per warp -> all
// LDS.128 are full-warp broadcasts.
__global__ __launch_bounds__(768, 1) void iter_kernel(int src, int dst, float* __restrict__ out) {
    extern __shared__ float4 sm[];          // [0,NPTS): points, then NSPLIT*128 partials
    float4* psum = sm + NPTS;
    const int b = blockIdx.y;

    const float4* gp = g_pts + b * NPTS;
    for (int i = threadIdx.x; i < NPTS; i += 768) sm[i] = gp[i];
    __syncthreads();

    const int ql = threadIdx.x & 63;        // query slot (q0=ql, q1=ql+64)
    const int s = threadIdx.x >> 6;         // j-chunk id (uniform within warp)
    const int qg0 = blockIdx.x * 128 + ql;
    const int qg1 = qg0 + 64;

    const float tg = 2.0f * GG;
    float4 y0 = g_y[src][b * NPTS + qg0];
    float4 y1 = g_y[src][b * NPTS + qg1];
    const u64 ax0 = pk2(tg * y0.x, tg * y0.x);
    const u64 ay0 = pk2(tg * y0.y, tg * y0.y);
    const u64 az0 = pk2(tg * y0.z, tg * y0.z);
    const float p0 = -GG * (y0.x * y0.x + y0.y * y0.y + y0.z * y0.z);
    const u64 pp0 = pk2(p0, p0);
    const u64 ax1 = pk2(tg * y1.x, tg * y1.x);
    const u64 ay1 = pk2(tg * y1.y, tg * y1.y);
    const u64 az1 = pk2(tg * y1.z, tg * y1.z);
    const float p1 = -GG * (y1.x * y1.x + y1.y * y1.y + y1.z * y1.z);
    const u64 pp1 = pk2(p1, p1);

    u64 a0x = 0ull, a0y = 0ull, a0z = 0ull, a0w = 0ull;
    u64 a1x = 0ull, a1y = 0ull, a1z = 0ull, a1w = 0ull;

    // Shared-window byte address of this warp's chunk (CHUNK float4s).
    unsigned saddr = (unsigned)__cvta_generic_to_shared(sm + s * CHUNK);

    #pragma unroll 2
    for (int i = 0; i < CHUNK / 2; i++) {   // 384 steps, 2 points x 2 queries
        u64 xx, yy, zz, bb;
        lds_2u64(saddr + 32u * i, xx, yy);        // {x0,x1},{y0,y1}
        lds_2u64(saddr + 32u * i + 16u, zz, bb);  // {z0,z1},{b0,b1}

        u64 t0 = add2(bb, pp0);
        t0 = fma2(az0, zz, t0);
        t0 = fma2(ay0, yy, t0);
        t0 = fma2(ax0, xx, t0);
        u64 t1 = add2(bb, pp1);
        t1 = fma2(az1, zz, t1);
        t1 = fma2(ay1, yy, t1);
        t1 = fma2(ax1, xx, t1);

        ex2_pair(t0);                       // 4x MUFU EX2 total, in place
        ex2_pair(t1);

        a0x = fma2(t0, xx, a0x);
        a0y = fma2(t0, yy, a0y);
        a0z = fma2(t0, zz, a0z);
        a0w = add2(a0w, t0);
        a1x = fma2(t1, xx, a1x);
        a1y = fma2(t1, yy, a1y);
        a1z = fma2(t1, zz, a1z);
        a1w = add2(a1w, t1);
    }

    float e0, e1;
    upk2(a0x, e0, e1); float s0x = e0 + e1;
    upk2(a0y, e0, e1); float s0y = e0 + e1;
    upk2(a0z, e0, e1); float s0z = e0 + e1;
    upk2(a0w, e0, e1); float s0w = e0 + e1;
    psum[s * 128 + ql] = make_float4(s0x, s0y, s0z, s0w);
    upk2(a1x, e0, e1); float s1x = e0 + e1;
    upk2(a1y, e0, e1); float s1y = e0 + e1;
    upk2(a1z, e0, e1); float s1z = e0 + e1;
    upk2(a1w, e0, e1); float s1w = e0 + e1;
    psum[s * 128 + ql + 64] = make_float4(s1x, s1y, s1z, s1w);
    __syncthreads();

    // Reduce the NSPLIT chunk-partials per query.
    if (threadIdx.x < 128) {
        float4 a = psum[threadIdx.x];
        #pragma unroll
        for (int k = 1; k < NSPLIT; k++) {
            float4 p2 = psum[k * 128 + threadIdx.x];
            a.x += p2.x; a.y += p2.y; a.z += p2.z; a.w += p2.w;
        }
        float inv = __fdividef(1.0f, a.w);
        float nx = a.x * inv, ny = a.y * inv, nz = a.z * inv;
        int qi = blockIdx.x * 128 + threadIdx.x;
        g_y[dst][b * NPTS + qi] = make_float4(nx, ny, nz, 0.f);
        if (out) {
            out[(b * 3 + 0) * NPTS + qi] = nx;
            out[(b * 3 + 1) * NPTS + qi] = ny;
            out[(b * 3 + 2) * NPTS + qi] = nz;
        }
    }
}

extern "C" void kernel_launch(void* const* d_in, const int* in_sizes, int n_in,
                              void* d_out, int out_size) {
    const float* x = (const float*)d_in[0];
    float* out = (float*)d_out;

    const size_t smem = (size_t)(NPTS + NSPLIT * 128) * sizeof(float4);  // 172032 B
    cudaFuncSetAttribute(iter_kernel, cudaFuncAttributeMaxDynamicSharedMemorySize, (int)smem);

    prep_kernel<<<(NB * NPTS + 255) / 256, 256>>>(x);

    dim3 grid(72, NB);
    for (int it = 0; it < 5; it++) {
        iter_kernel<<<grid, 768, smem>>>(it & 1, (it & 1) ^ 1, (it == 4) ? out : nullptr);
    }
}